// round 15
// baseline (speedup 1.0000x reference)
#include <cuda_runtime.h>
#include <math.h>
#include <stdint.h>

#define NROWS 16384
#define DDIM  256
#define KCB   8192

#define OFF_Q   16384
#define OFF_ST  (16384 + NROWS*DDIM)
#define OFF_SC  (16384 + 2*NROWS*DDIM)

#define SLOTS 64
#define EPS 5e-5f

#define TM   64                   // rows per rowblk
#define TKT  128                  // codebook cols per tile
#define DC   16                   // d per stage
#define KSLICE 1024
#define NRB  (NROWS / TM)         // 256
#define NSL  (KCB / KSLICE)       // 8
#define NUNITS (NRB * NSL)        // 2048
#define USTAGES 128               // 8 tiles x 16 d-chunks
#define GRID_SCAN 296
#define NBUF 4

#define A_STRIDE 68               // words per d-row (64 rows + 4 pad), 272B (16B-aligned)
#define AW (DDIM * A_STRIDE)      // 17408 words
#define BW (DC * TKT)             // 2048 words per buffer
#define SMEM_WORDS (AW + NBUF * BW + TM + 16)
#define SMEM_BYTES (SMEM_WORDS * 4)   // 102,720 B -> 2 CTAs/SM

#define CBW (DDIM * KCB)          // codebook elements

__device__ float  d_xtT[(size_t)NROWS * DDIM];   // [rbi][d][row64] fp32
__device__ float  d_ctT[(size_t)DDIM * KCB];     // [d][col] fp32
__device__ float  d_hist[KCB];
__device__ int    d_bidx[NROWS];
__device__ int    d_cnt[NROWS];
__device__ int    d_cand[NROWS * SLOTS];
__device__ double d_sqsum;
__device__ int    d_wq;

// ---------------------------------------------------------------------------
// helpers
// ---------------------------------------------------------------------------
__device__ __forceinline__ uint32_t smem_u32(const void* p) {
    uint32_t a;
    asm("{ .reg .u64 t; cvta.to.shared.u64 t, %1; cvt.u32.u64 %0, t; }" : "=r"(a) : "l"(p));
    return a;
}
__device__ __forceinline__ void cp_async16(uint32_t dst, const void* src) {
    asm volatile("cp.async.cg.shared.global [%0], [%1], 16;" :: "r"(dst), "l"(src) : "memory");
}
#define CP_COMMIT() asm volatile("cp.async.commit_group;" ::: "memory")
#define CP_WAIT(n)  asm volatile("cp.async.wait_group %0;" :: "n"(n) : "memory")

__device__ __forceinline__ int   fmap(float f)  { int i = __float_as_int(f); return i < 0 ? i ^ 0x7FFFFFFF : i; }
__device__ __forceinline__ float funmap(int u)  { if (u < 0) u ^= 0x7FFFFFFF; return __int_as_float(u); }

__device__ __forceinline__ void fma2(unsigned long long& d, unsigned long long a,
                                     unsigned long long b) {
    asm("fma.rn.f32x2 %0, %1, %2, %0;" : "+l"(d) : "l"(a), "l"(b));
}
__device__ __forceinline__ unsigned long long pack_dup(float f) {
    unsigned long long o;
    unsigned u = __float_as_uint(f);
    asm("mov.b64 %0, {%1, %1};" : "=l"(o) : "r"(u));
    return o;
}
__device__ __forceinline__ void unpack2(unsigned long long v, float& lo, float& hi) {
    unsigned a, b;
    asm("mov.b64 {%0, %1}, %2;" : "=r"(a), "=r"(b) : "l"(v));
    lo = __uint_as_float(a); hi = __uint_as_float(b);
}

// ---------------------------------------------------------------------------
// Kernel 1: fused prep — transpose latents + codebook, zero accumulators
// ---------------------------------------------------------------------------
__global__ __launch_bounds__(256) void k_prep(const float* __restrict__ lat,
                                              const float* __restrict__ cb) {
    int g = blockIdx.x * 256 + threadIdx.x;          // 4,194,304 threads
    {   // latents: [row][d] -> [rbi][d][row64]
        int row = g & 63, d = (g >> 6) & 255, rbi = g >> 14;
        d_xtT[g] = lat[((size_t)(rbi * TM + row)) * DDIM + d];
    }
    if (g < CBW) {   // codebook: [col][d] -> [d][col]
        int col = g & (KCB - 1), d = g >> 13;
        d_ctT[g] = cb[(size_t)col * DDIM + d];
    }
    if (g < KCB)   d_hist[g] = 0.f;
    if (g < NROWS) d_cnt[g]  = 0;
    if (g == 0)  { d_sqsum   = 0.0; d_wq = 0; }
}

// ---------------------------------------------------------------------------
// Kernel 2: persistent work-queue FFMA2 scan, 2 CTAs/SM, 4-deep cp.async ring
// unit = 64 rows x 1024 codes; 256 threads (tx 16 col-groups, ty 16 row-groups)
// thread tile: 4 rows x 8 cols (two 4-col groups 64 apart -> conflict-free LDS)
// ---------------------------------------------------------------------------
#define ISSUE_B(s_) do {                                                        \
    int t_ = (s_) >> 4, c_ = (s_) & 15, buf_ = (s_) & (NBUF - 1);               \
    const float* gB_ = d_ctT + (size_t)(c_ * DC) * KCB + ksl * KSLICE + t_ * TKT; \
    _Pragma("unroll")                                                           \
    for (int i_ = 0; i_ < 2; i_++) {                                            \
        int s2_ = tid + i_ * 256;                                               \
        int dd_ = s2_ >> 5, ch_ = s2_ & 31;                                     \
        cp_async16(sbB + (uint32_t)(buf_ * BW + dd_ * TKT + ch_ * 4) * 4,       \
                   gB_ + (size_t)dd_ * KCB + ch_ * 4);                          \
    }                                                                           \
    CP_COMMIT();                                                                \
} while (0)

__global__ __launch_bounds__(256, 2) void k_scan_f2() {
    extern __shared__ __align__(16) float smf[];
    float* As = smf;                        // [d][row] stride 68
    float* Bs = smf + AW;                   // NBUF buffers [16 dd][128 col]
    int*   Rb = (int*)(smf + AW + NBUF * BW);
    __shared__ int s_unit;

    const int tid = threadIdx.x;
    const int tx = tid & 15, ty = tid >> 4;
    const uint32_t sbA = smem_u32(As);
    const uint32_t sbB = smem_u32(Bs);

    for (;;) {
        if (tid == 0) s_unit = atomicAdd(&d_wq, 1);
        __syncthreads();                    // also fences prev unit's Rb readers
        const int u = s_unit;
        if (u >= NUNITS) break;
        const int rbi = u >> 3, ksl = u & 7;
        const int rowblk = rbi * TM;

        if (tid < TM) Rb[tid] = fmap(-3.0e38f);

        // issue A tile: exactly DDIM*TM/4 = 4096 16B chunks = 16 iterations
        {
            const float* gA = d_xtT + (size_t)rbi * (DDIM * TM);
#pragma unroll
            for (int i = 0; i < 16; i++) {
                int s2 = tid + i * 256;            // 0..4095
                int d = s2 >> 4, rg = s2 & 15;     // d in 0..255, rg in 0..15
                cp_async16(sbA + (uint32_t)(d * A_STRIDE + rg * 4) * 4,
                           gA + (size_t)d * TM + rg * 4);
            }
            CP_COMMIT();
        }
        ISSUE_B(0);
        ISSUE_B(1);
        ISSUE_B(2);

        unsigned long long acc[4][4];
#pragma unroll
        for (int r = 0; r < 4; r++)
#pragma unroll
            for (int j = 0; j < 4; j++) acc[r][j] = 0ull;

        for (int s = 0; s < USTAGES; s++) {
            const int c = s & 15, t = s >> 4;
            const float* B = Bs + (s & (NBUF - 1)) * BW;
            if (s + 2 < USTAGES)      { CP_WAIT(2); }
            else if (s + 1 < USTAGES) { CP_WAIT(1); }
            else                      { CP_WAIT(0); }
            __syncthreads();
            if (s + 3 < USTAGES) ISSUE_B(s + 3);

#pragma unroll
            for (int dd = 0; dd < DC; dd++) {
                float4 af = *(const float4*)(As + (size_t)(c * DC + dd) * A_STRIDE + 4 * ty);
                unsigned long long a0 = pack_dup(af.x), a1 = pack_dup(af.y);
                unsigned long long a2 = pack_dup(af.z), a3 = pack_dup(af.w);
                const float* bp = B + (size_t)dd * TKT;
                ulonglong2 b01 = *(const ulonglong2*)(bp + 4 * tx);
                ulonglong2 b23 = *(const ulonglong2*)(bp + 64 + 4 * tx);
                fma2(acc[0][0], a0, b01.x); fma2(acc[1][0], a1, b01.x);
                fma2(acc[2][0], a2, b01.x); fma2(acc[3][0], a3, b01.x);
                fma2(acc[0][1], a0, b01.y); fma2(acc[1][1], a1, b01.y);
                fma2(acc[2][1], a2, b01.y); fma2(acc[3][1], a3, b01.y);
                fma2(acc[0][2], a0, b23.x); fma2(acc[1][2], a1, b23.x);
                fma2(acc[2][2], a2, b23.x); fma2(acc[3][2], a3, b23.x);
                fma2(acc[0][3], a0, b23.y); fma2(acc[1][3], a1, b23.y);
                fma2(acc[2][3], a2, b23.y); fma2(acc[3][3], a3, b23.y);
            }

            if (c == 15) {      // end of 128-col k-tile: max + collect + reset
                const int kbase = ksl * KSLICE + t * TKT;
#pragma unroll
                for (int r = 0; r < 4; r++) {
                    float v8[8];
#pragma unroll
                    for (int j = 0; j < 4; j++) {
                        unpack2(acc[r][j], v8[2 * j], v8[2 * j + 1]);
                        acc[r][j] = 0ull;
                    }
                    float mx = v8[0];
#pragma unroll
                    for (int cc = 1; cc < 8; cc++) mx = fmaxf(mx, v8[cc]);
                    mx = fmaxf(mx, __shfl_xor_sync(0xffffffffu, mx, 1));
                    mx = fmaxf(mx, __shfl_xor_sync(0xffffffffu, mx, 2));
                    mx = fmaxf(mx, __shfl_xor_sync(0xffffffffu, mx, 4));
                    mx = fmaxf(mx, __shfl_xor_sync(0xffffffffu, mx, 8));
                    if (tx == 0) {
                        int mm = fmap(mx);
                        if (mm > Rb[4 * ty + r]) atomicMax(&Rb[4 * ty + r], mm);
                    }
                    // own tile max always in threshold; stale Rb reads only over-collect
                    const float thr = fmaxf(funmap(Rb[4 * ty + r]), mx) - EPS;
                    const int grow = rowblk + 4 * ty + r;
#pragma unroll
                    for (int cc = 0; cc < 8; cc++) {
                        if (v8[cc] > thr) {
                            int pos = atomicAdd(&d_cnt[grow], 1);
                            int col = (cc < 4) ? (kbase + 4 * tx + cc)
                                               : (kbase + 64 + 4 * tx + (cc - 4));
                            if (pos < SLOTS)
                                d_cand[grow * SLOTS + pos] = col;
                        }
                    }
                }
            }
        }
    }
}

// ---------------------------------------------------------------------------
// Kernel 3: exact re-evaluation of candidates with double-precision dots.
// Reference rounding: q = fl( fl(xn2 + cn2) - 2*dot ). cn2 <= 256/8192^2 =
// 3.8e-6 < half-ulp(xn2) (xn2 >= 128 w.p. 1) => fl(xn2+cn2) == xn2, so cn2
// is dropped. Double dot error ~2^-50 rel << fp32 ulp => rounding to float
// reproduces the correctly-rounded fp32 dot. Argmin, lowest-index ties.
// ---------------------------------------------------------------------------
__global__ __launch_bounds__(256) void k_exact(const float* __restrict__ lat,
                                               const float* __restrict__ cb,
                                               float* __restrict__ out) {
    const int tid = threadIdx.x;
    const int lane = tid & 31, w = tid >> 5;
    const int row = blockIdx.x * 8 + w;

    float x[8];
    {
        const float4* xr = (const float4*)(lat + (size_t)row * DDIM);
        float4 a = xr[lane * 2], b = xr[lane * 2 + 1];
        x[0]=a.x; x[1]=a.y; x[2]=a.z; x[3]=a.w;
        x[4]=b.x; x[5]=b.y; x[6]=b.z; x[7]=b.w;
    }
    double xs = 0.0;
#pragma unroll
    for (int i = 0; i < 8; i++) xs += (double)x[i] * (double)x[i];
#pragma unroll
    for (int o = 16; o; o >>= 1) xs += __shfl_xor_sync(0xffffffffu, xs, o);
    float xn2 = (float)xs;

    int   n     = d_cnt[row];
    bool  fallb = (n > SLOTS);
    int   ncand = fallb ? KCB : n;

    float bestq = 3.4e38f;
    int   besti = 0;

    for (int c = 0; c < ncand; c++) {
        int idx = fallb ? c : d_cand[row * SLOTS + c];
        const float4* cr = (const float4*)(cb + (size_t)idx * DDIM);
        float4 a = cr[lane * 2], b = cr[lane * 2 + 1];

        double s = 0.0;
        s = fma((double)x[0], (double)a.x, s);
        s = fma((double)x[1], (double)a.y, s);
        s = fma((double)x[2], (double)a.z, s);
        s = fma((double)x[3], (double)a.w, s);
        s = fma((double)x[4], (double)b.x, s);
        s = fma((double)x[5], (double)b.y, s);
        s = fma((double)x[6], (double)b.z, s);
        s = fma((double)x[7], (double)b.w, s);
#pragma unroll
        for (int o = 16; o; o >>= 1) s += __shfl_xor_sync(0xffffffffu, s, o);

        if (lane == 0) {
            float df = (float)s;
            float q  = __fadd_rn(xn2, -__fmul_rn(2.f, df));
            if (q < bestq || (q == bestq && idx < besti)) { bestq = q; besti = idx; }
        }
    }
    if (lane == 0) {
        d_bidx[row] = besti;
        out[row] = (float)besti;
    }
}

// ---------------------------------------------------------------------------
// Kernel 4: gather -> quantized + st_quantized, MSE partials, histogram
// ---------------------------------------------------------------------------
__global__ __launch_bounds__(256) void k_gather(const float* __restrict__ lat,
                                                const float* __restrict__ mask,
                                                const float* __restrict__ cb,
                                                float* __restrict__ out) {
    __shared__ float wsum[8];
    const int tid = threadIdx.x;
    const int lane = tid & 31, w = tid >> 5;
    const int row = blockIdx.x * 8 + w;

    int idx = d_bidx[row];
    const float4* x = (const float4*)(lat + (size_t)row * DDIM);
    const float4* c = (const float4*)(cb + (size_t)idx * DDIM);
    float4* q  = (float4*)(out + OFF_Q  + (size_t)row * DDIM);
    float4* st = (float4*)(out + OFF_ST + (size_t)row * DDIM);

    float s = 0.f;
#pragma unroll
    for (int i = lane; i < DDIM / 4; i += 32) {
        float4 cv = c[i], xv = x[i];
        q[i]  = cv;
        st[i] = cv;
        float d0 = xv.x - cv.x, d1 = xv.y - cv.y;
        float d2 = xv.z - cv.z, d3 = xv.w - cv.w;
        s += d0 * d0 + d1 * d1 + d2 * d2 + d3 * d3;
    }
#pragma unroll
    for (int o = 16; o; o >>= 1) s += __shfl_xor_sync(0xffffffffu, s, o);
    if (lane == 0) {
        wsum[w] = s;
        atomicAdd(&d_hist[idx], mask[row]);
    }
    __syncthreads();
    if (tid == 0) {
        double t = 0.0;
#pragma unroll
        for (int i = 0; i < 8; i++) t += (double)wsum[i];
        atomicAdd(&d_sqsum, t);
    }
}

// ---------------------------------------------------------------------------
// Kernel 5: finalize losses + perplexity
// ---------------------------------------------------------------------------
__global__ void k_final(const float* __restrict__ mask, float* __restrict__ out) {
    __shared__ float sh[256];
    const int tid = threadIdx.x;

    float m = 0.f;
    for (int i = tid; i < NROWS; i += 256) m += mask[i];
    sh[tid] = m; __syncthreads();
    for (int o = 128; o; o >>= 1) { if (tid < o) sh[tid] += sh[tid + o]; __syncthreads(); }
    float denom = fmaxf(sh[0], 1.0f);
    __syncthreads();

    float e = 0.f;
    for (int k2 = tid; k2 < KCB; k2 += 256) {
        float p = d_hist[k2] / denom;
        e += p * logf(p + 1e-8f);
    }
    sh[tid] = e; __syncthreads();
    for (int o = 128; o; o >>= 1) { if (tid < o) sh[tid] += sh[tid + o]; __syncthreads(); }

    if (tid == 0) {
        double mse = d_sqsum / (double)((size_t)NROWS * DDIM);
        out[OFF_SC + 0] = (float)(mse * 0.25);
        out[OFF_SC + 1] = (float)mse;
        out[OFF_SC + 2] = expf(-sh[0]);
    }
}

// ---------------------------------------------------------------------------
extern "C" void kernel_launch(void* const* d_in, const int* in_sizes, int n_in,
                              void* d_out, int out_size) {
    const float* lat  = (const float*)d_in[0];
    const float* mask = (const float*)d_in[1];
    const float* cb   = (const float*)d_in[2];
    float* out = (float*)d_out;

    cudaFuncSetAttribute(k_scan_f2, cudaFuncAttributeMaxDynamicSharedMemorySize, SMEM_BYTES);

    k_prep   <<<(NROWS * DDIM) / 256, 256>>>(lat, cb);
    k_scan_f2<<<GRID_SCAN, 256, SMEM_BYTES>>>();
    k_exact  <<<NROWS / 8, 256>>>(lat, cb, out);
    k_gather <<<NROWS / 8, 256>>>(lat, mask, cb, out);
    k_final  <<<1, 256>>>(mask, out);
}

// round 16
// speedup vs baseline: 1.3391x; 1.3391x over previous
#include <cuda_runtime.h>
#include <math.h>
#include <stdint.h>

#define NROWS 16384
#define DDIM  256
#define KCB   8192

#define OFF_Q   16384
#define OFF_ST  (16384 + NROWS*DDIM)
#define OFF_SC  (16384 + 2*NROWS*DDIM)

#define SLOTS 64
#define EPS 5e-5f

#define TM   64                   // rows per rowblk
#define TKT  128                  // codebook cols per tile
#define DC   16                   // d per stage
#define KSLICE 1024
#define NRB  (NROWS / TM)         // 256
#define NSL  (KCB / KSLICE)       // 8
#define NUNITS (NRB * NSL)        // 2048
#define USTAGES 128               // 8 tiles x 16 d-chunks
#define GRID_SCAN 296
#define NBUF 4

#define A_STRIDE 68               // words per d-row (64 rows + 4 pad), 272B (16B-aligned)
#define AW (DDIM * A_STRIDE)      // 17408 words
#define BW (DC * TKT)             // 2048 words per buffer
#define SMEM_WORDS (AW + NBUF * BW + TM + 16)
#define SMEM_BYTES (SMEM_WORDS * 4)   // 102,720 B -> 2 CTAs/SM

__device__ float  d_xtT[(size_t)NROWS * DDIM];   // [rbi][d][row64] fp32
__device__ float  d_ctT[(size_t)DDIM * KCB];     // [d][col] fp32
__device__ float  d_hist[KCB];
__device__ int    d_cnt[NROWS];
__device__ int    d_cand[NROWS * SLOTS];
__device__ double d_sqsum;
__device__ int    d_wq;

// ---------------------------------------------------------------------------
// helpers
// ---------------------------------------------------------------------------
__device__ __forceinline__ uint32_t smem_u32(const void* p) {
    uint32_t a;
    asm("{ .reg .u64 t; cvta.to.shared.u64 t, %1; cvt.u32.u64 %0, t; }" : "=r"(a) : "l"(p));
    return a;
}
__device__ __forceinline__ void cp_async16(uint32_t dst, const void* src) {
    asm volatile("cp.async.cg.shared.global [%0], [%1], 16;" :: "r"(dst), "l"(src) : "memory");
}
#define CP_COMMIT() asm volatile("cp.async.commit_group;" ::: "memory")
#define CP_WAIT(n)  asm volatile("cp.async.wait_group %0;" :: "n"(n) : "memory")

__device__ __forceinline__ int   fmap(float f)  { int i = __float_as_int(f); return i < 0 ? i ^ 0x7FFFFFFF : i; }
__device__ __forceinline__ float funmap(int u)  { if (u < 0) u ^= 0x7FFFFFFF; return __int_as_float(u); }

__device__ __forceinline__ void fma2(unsigned long long& d, unsigned long long a,
                                     unsigned long long b) {
    asm("fma.rn.f32x2 %0, %1, %2, %0;" : "+l"(d) : "l"(a), "l"(b));
}
__device__ __forceinline__ unsigned long long pack_dup(float f) {
    unsigned long long o;
    unsigned u = __float_as_uint(f);
    asm("mov.b64 %0, {%1, %1};" : "=l"(o) : "r"(u));
    return o;
}
__device__ __forceinline__ void unpack2(unsigned long long v, float& lo, float& hi) {
    unsigned a, b;
    asm("mov.b64 {%0, %1}, %2;" : "=r"(a), "=r"(b) : "l"(v));
    lo = __uint_as_float(a); hi = __uint_as_float(b);
}

// ---------------------------------------------------------------------------
// Kernel 1a: pre-transpose latents + zero accumulators/work queue (fused)
// ---------------------------------------------------------------------------
__global__ __launch_bounds__(256) void k_prep_x(const float* __restrict__ lat) {
    int g = blockIdx.x * 256 + threadIdx.x;          // 4,194,304 elements
    int row = g & 63, d = (g >> 6) & 255, rbi = g >> 14;
    d_xtT[g] = lat[((size_t)(rbi * TM + row)) * DDIM + d];
    if (g < KCB)   d_hist[g] = 0.f;
    if (g < NROWS) d_cnt[g]  = 0;
    if (g == 0)  { d_sqsum   = 0.0; d_wq = 0; }
}

// ---------------------------------------------------------------------------
// Kernel 1b: pre-transpose codebook -> [d][col]  (coalesced writes)
// ---------------------------------------------------------------------------
__global__ __launch_bounds__(256) void k_prep_c(const float* __restrict__ cb) {
    int g = blockIdx.x * 256 + threadIdx.x;          // 2,097,152 elements
    int col = g & (KCB - 1), d = g >> 13;
    d_ctT[g] = cb[(size_t)col * DDIM + d];
}

// ---------------------------------------------------------------------------
// Kernel 2: persistent work-queue FFMA2 scan, 2 CTAs/SM, 4-deep cp.async ring
// unit = 64 rows x 1024 codes; 256 threads (tx 16 col-groups, ty 16 row-groups)
// thread tile: 4 rows x 8 cols (two 4-col groups 64 apart -> conflict-free LDS)
// ---------------------------------------------------------------------------
#define ISSUE_B(s_) do {                                                        \
    int t_ = (s_) >> 4, c_ = (s_) & 15, buf_ = (s_) & (NBUF - 1);               \
    const float* gB_ = d_ctT + (size_t)(c_ * DC) * KCB + ksl * KSLICE + t_ * TKT; \
    _Pragma("unroll")                                                           \
    for (int i_ = 0; i_ < 2; i_++) {                                            \
        int s2_ = tid + i_ * 256;                                               \
        int dd_ = s2_ >> 5, ch_ = s2_ & 31;                                     \
        cp_async16(sbB + (uint32_t)(buf_ * BW + dd_ * TKT + ch_ * 4) * 4,       \
                   gB_ + (size_t)dd_ * KCB + ch_ * 4);                          \
    }                                                                           \
    CP_COMMIT();                                                                \
} while (0)

__global__ __launch_bounds__(256, 2) void k_scan_f2() {
    extern __shared__ __align__(16) float smf[];
    float* As = smf;                        // [d][row] stride 68
    float* Bs = smf + AW;                   // NBUF buffers [16 dd][128 col]
    int*   Rb = (int*)(smf + AW + NBUF * BW);
    __shared__ int s_unit;

    const int tid = threadIdx.x;
    const int tx = tid & 15, ty = tid >> 4;
    const uint32_t sbA = smem_u32(As);
    const uint32_t sbB = smem_u32(Bs);

    for (;;) {
        if (tid == 0) s_unit = atomicAdd(&d_wq, 1);
        __syncthreads();                    // also fences prev unit's Rb readers
        const int u = s_unit;
        if (u >= NUNITS) break;
        const int rbi = u >> 3, ksl = u & 7;
        const int rowblk = rbi * TM;

        if (tid < TM) Rb[tid] = fmap(-3.0e38f);

        // issue A tile: exactly DDIM*TM/4 = 4096 16B chunks = 16 iterations
        {
            const float* gA = d_xtT + (size_t)rbi * (DDIM * TM);
#pragma unroll
            for (int i = 0; i < 16; i++) {
                int s2 = tid + i * 256;            // 0..4095
                int d = s2 >> 4, rg = s2 & 15;     // d in 0..255, rg in 0..15
                cp_async16(sbA + (uint32_t)(d * A_STRIDE + rg * 4) * 4,
                           gA + (size_t)d * TM + rg * 4);
            }
            CP_COMMIT();
        }
        ISSUE_B(0);
        ISSUE_B(1);
        ISSUE_B(2);

        unsigned long long acc[4][4];
#pragma unroll
        for (int r = 0; r < 4; r++)
#pragma unroll
            for (int j = 0; j < 4; j++) acc[r][j] = 0ull;

        for (int s = 0; s < USTAGES; s++) {
            const int c = s & 15, t = s >> 4;
            const float* B = Bs + (s & (NBUF - 1)) * BW;
            if (s + 2 < USTAGES)      { CP_WAIT(2); }
            else if (s + 1 < USTAGES) { CP_WAIT(1); }
            else                      { CP_WAIT(0); }
            __syncthreads();
            if (s + 3 < USTAGES) ISSUE_B(s + 3);

#pragma unroll
            for (int dd = 0; dd < DC; dd++) {
                float4 af = *(const float4*)(As + (size_t)(c * DC + dd) * A_STRIDE + 4 * ty);
                unsigned long long a0 = pack_dup(af.x), a1 = pack_dup(af.y);
                unsigned long long a2 = pack_dup(af.z), a3 = pack_dup(af.w);
                const float* bp = B + (size_t)dd * TKT;
                ulonglong2 b01 = *(const ulonglong2*)(bp + 4 * tx);
                ulonglong2 b23 = *(const ulonglong2*)(bp + 64 + 4 * tx);
                fma2(acc[0][0], a0, b01.x); fma2(acc[1][0], a1, b01.x);
                fma2(acc[2][0], a2, b01.x); fma2(acc[3][0], a3, b01.x);
                fma2(acc[0][1], a0, b01.y); fma2(acc[1][1], a1, b01.y);
                fma2(acc[2][1], a2, b01.y); fma2(acc[3][1], a3, b01.y);
                fma2(acc[0][2], a0, b23.x); fma2(acc[1][2], a1, b23.x);
                fma2(acc[2][2], a2, b23.x); fma2(acc[3][2], a3, b23.x);
                fma2(acc[0][3], a0, b23.y); fma2(acc[1][3], a1, b23.y);
                fma2(acc[2][3], a2, b23.y); fma2(acc[3][3], a3, b23.y);
            }

            if (c == 15) {      // end of 128-col k-tile: max + collect + reset
                const int kbase = ksl * KSLICE + t * TKT;
#pragma unroll
                for (int r = 0; r < 4; r++) {
                    float v8[8];
#pragma unroll
                    for (int j = 0; j < 4; j++) {
                        unpack2(acc[r][j], v8[2 * j], v8[2 * j + 1]);
                        acc[r][j] = 0ull;
                    }
                    float mx = v8[0];
#pragma unroll
                    for (int cc = 1; cc < 8; cc++) mx = fmaxf(mx, v8[cc]);
                    mx = fmaxf(mx, __shfl_xor_sync(0xffffffffu, mx, 1));
                    mx = fmaxf(mx, __shfl_xor_sync(0xffffffffu, mx, 2));
                    mx = fmaxf(mx, __shfl_xor_sync(0xffffffffu, mx, 4));
                    mx = fmaxf(mx, __shfl_xor_sync(0xffffffffu, mx, 8));
                    if (tx == 0) {
                        int mm = fmap(mx);
                        if (mm > Rb[4 * ty + r]) atomicMax(&Rb[4 * ty + r], mm);
                    }
                    // own tile max always in threshold; stale Rb reads only over-collect
                    const float thr = fmaxf(funmap(Rb[4 * ty + r]), mx) - EPS;
                    const int grow = rowblk + 4 * ty + r;
#pragma unroll
                    for (int cc = 0; cc < 8; cc++) {
                        if (v8[cc] > thr) {
                            int pos = atomicAdd(&d_cnt[grow], 1);
                            int col = (cc < 4) ? (kbase + 4 * tx + cc)
                                               : (kbase + 64 + 4 * tx + (cc - 4));
                            if (pos < SLOTS)
                                d_cand[grow * SLOTS + pos] = col;
                        }
                    }
                }
            }
        }
    }
}

// ---------------------------------------------------------------------------
// Kernel 3: exact re-rank (half-warp per candidate, compensated fp32 dots)
// + fused gather / MSE partials / histogram.
// Reference rounding: q = fl( fl(xn2+cn2) - 2*dot_f ). cn2 <= 3.81e-6 <
// half-ulp(xn2>=128) => fl(xn2+cn2) == xn2 (validated bit-identical in R15),
// so cn2 is dropped. The compensated dot is correctly rounded (order-
// independent), so half-warp reduction gives identical besti. Lowest-index ties.
// ---------------------------------------------------------------------------
__global__ __launch_bounds__(256) void k_exact_g(const float* __restrict__ lat,
                                                 const float* __restrict__ mask,
                                                 const float* __restrict__ cb,
                                                 float* __restrict__ out) {
    __shared__ float wsum[8];
    const int tid = threadIdx.x;
    const int lane = tid & 31, w = tid >> 5;
    const int hw = lane >> 4, hl = lane & 15;     // half-warp id, half-lane
    const int row = blockIdx.x * 8 + w;

    // each lane covers 16 contiguous elements [hl*16 .. hl*16+15]
    float x[16];
    {
        const float4* xr = (const float4*)(lat + (size_t)row * DDIM);
#pragma unroll
        for (int i = 0; i < 4; i++) {
            float4 v = xr[hl * 4 + i];
            x[4 * i + 0] = v.x; x[4 * i + 1] = v.y;
            x[4 * i + 2] = v.z; x[4 * i + 3] = v.w;
        }
    }
    double xs = 0.0;
#pragma unroll
    for (int i = 0; i < 16; i++) xs += (double)x[i] * (double)x[i];
#pragma unroll
    for (int o = 8; o; o >>= 1) xs += __shfl_xor_sync(0xffffffffu, xs, o);
    float xn2 = (float)xs;          // both halves hold the full-row norm

    int   n     = d_cnt[row];
    bool  fallb = (n > SLOTS);
    int   ncand = fallb ? KCB : n;

    float bestq = 3.4e38f;
    int   besti = 0x7FFFFFFF;

    for (int c = 0; c < ncand; c += 2) {
        const int  ci  = c + hw;
        const bool act = (ci < ncand);
        const int  idx = act ? (fallb ? ci : d_cand[row * SLOTS + ci]) : 0;
        const float4* cr = (const float4*)(cb + (size_t)idx * DDIM);

        float hi = 0.f, co = 0.f;
#pragma unroll
        for (int i = 0; i < 4; i++) {
            float4 v = cr[hl * 4 + i];
            float cv[4] = {v.x, v.y, v.z, v.w};
#pragma unroll
            for (int k = 0; k < 4; k++) {
                float xx = x[4 * i + k];
                float p = __fmul_rn(xx, cv[k]);
                float e = __fmaf_rn(xx, cv[k], -p);
                float t = __fadd_rn(hi, p);
                float z = __fsub_rn(t, hi);
                float q2 = __fadd_rn(__fsub_rn(hi, __fsub_rn(t, z)), __fsub_rn(p, z));
                hi = t; co = __fadd_rn(co, __fadd_rn(q2, e));
            }
        }
#pragma unroll
        for (int o = 8; o; o >>= 1) {
            float h2 = __shfl_xor_sync(0xffffffffu, hi, o);
            float c2 = __shfl_xor_sync(0xffffffffu, co, o);
            float t = __fadd_rn(hi, h2);
            float z = __fsub_rn(t, hi);
            float q2 = __fadd_rn(__fsub_rn(hi, __fsub_rn(t, z)), __fsub_rn(h2, z));
            hi = t; co = __fadd_rn(co, __fadd_rn(c2, q2));
        }
        if (hl == 0 && act) {
            float df = __fadd_rn(hi, co);                   // correctly-rounded dot
            float q  = __fadd_rn(xn2, -__fmul_rn(2.f, df)); // fl(xn2 - 2*dot)
            if (q < bestq || (q == bestq && idx < besti)) { bestq = q; besti = idx; }
        }
    }
    // merge the two half-warp winners (held at lanes 0 and 16)
    {
        float q1 = __shfl_sync(0xffffffffu, bestq, 16);
        int   i1 = __shfl_sync(0xffffffffu, besti, 16);
        if (lane == 0) {
            if (q1 < bestq || (q1 == bestq && i1 < besti)) { bestq = q1; besti = i1; }
            out[row] = (float)besti;
        }
    }
    const int bi = __shfl_sync(0xffffffffu, besti, 0);

    // fused gather: quantized + st_quantized + MSE partial + histogram
    {
        const float4* xr = (const float4*)(lat + (size_t)row * DDIM);
        const float4* c4 = (const float4*)(cb + (size_t)bi * DDIM);
        float4* q4  = (float4*)(out + OFF_Q  + (size_t)row * DDIM);
        float4* st4 = (float4*)(out + OFF_ST + (size_t)row * DDIM);
        float s = 0.f;
#pragma unroll
        for (int i = lane; i < DDIM / 4; i += 32) {
            float4 cv = c4[i], xv = xr[i];
            q4[i]  = cv;
            st4[i] = cv;
            float d0 = xv.x - cv.x, d1 = xv.y - cv.y;
            float d2 = xv.z - cv.z, d3 = xv.w - cv.w;
            s += d0 * d0 + d1 * d1 + d2 * d2 + d3 * d3;
        }
#pragma unroll
        for (int o = 16; o; o >>= 1) s += __shfl_xor_sync(0xffffffffu, s, o);
        if (lane == 0) {
            wsum[w] = s;
            atomicAdd(&d_hist[bi], mask[row]);
        }
    }
    __syncthreads();
    if (tid == 0) {
        double t = 0.0;
#pragma unroll
        for (int i = 0; i < 8; i++) t += (double)wsum[i];
        atomicAdd(&d_sqsum, t);
    }
}

// ---------------------------------------------------------------------------
// Kernel 4: finalize losses + perplexity
// ---------------------------------------------------------------------------
__global__ void k_final(const float* __restrict__ mask, float* __restrict__ out) {
    __shared__ float sh[256];
    const int tid = threadIdx.x;

    float m = 0.f;
    for (int i = tid; i < NROWS; i += 256) m += mask[i];
    sh[tid] = m; __syncthreads();
    for (int o = 128; o; o >>= 1) { if (tid < o) sh[tid] += sh[tid + o]; __syncthreads(); }
    float denom = fmaxf(sh[0], 1.0f);
    __syncthreads();

    float e = 0.f;
    for (int k2 = tid; k2 < KCB; k2 += 256) {
        float p = d_hist[k2] / denom;
        e += p * logf(p + 1e-8f);
    }
    sh[tid] = e; __syncthreads();
    for (int o = 128; o; o >>= 1) { if (tid < o) sh[tid] += sh[tid + o]; __syncthreads(); }

    if (tid == 0) {
        double mse = d_sqsum / (double)((size_t)NROWS * DDIM);
        out[OFF_SC + 0] = (float)(mse * 0.25);
        out[OFF_SC + 1] = (float)mse;
        out[OFF_SC + 2] = expf(-sh[0]);
    }
}

// ---------------------------------------------------------------------------
extern "C" void kernel_launch(void* const* d_in, const int* in_sizes, int n_in,
                              void* d_out, int out_size) {
    const float* lat  = (const float*)d_in[0];
    const float* mask = (const float*)d_in[1];
    const float* cb   = (const float*)d_in[2];
    float* out = (float*)d_out;

    cudaFuncSetAttribute(k_scan_f2, cudaFuncAttributeMaxDynamicSharedMemorySize, SMEM_BYTES);

    k_prep_x <<<(NROWS * DDIM) / 256, 256>>>(lat);
    k_prep_c <<<(DDIM * KCB) / 256, 256>>>(cb);
    k_scan_f2<<<GRID_SCAN, 256, SMEM_BYTES>>>();
    k_exact_g<<<NROWS / 8, 256>>>(lat, mask, cb, out);
    k_final  <<<1, 256>>>(mask, out);
}

// round 17
// speedup vs baseline: 1.3873x; 1.0360x over previous
#include <cuda_runtime.h>
#include <math.h>
#include <stdint.h>

#define NROWS 16384
#define DDIM  256
#define KCB   8192

#define OFF_Q   16384
#define OFF_ST  (16384 + NROWS*DDIM)
#define OFF_SC  (16384 + 2*NROWS*DDIM)

#define SLOTS 64
#define EPS 5e-5f

#define TM   64                   // rows per rowblk
#define TKT  128                  // codebook cols per tile
#define DC   16                   // d per stage
#define KSLICE 1024
#define NRB  (NROWS / TM)         // 256
#define NSL  (KCB / KSLICE)       // 8
#define NUNITS (NRB * NSL)        // 2048
#define USTAGES 128               // 8 tiles x 16 d-chunks
#define GRID_SCAN 296
#define NBUF 4

#define A_STRIDE 68               // words per d-row (64 rows + 4 pad), 272B (16B-aligned)
#define AW (DDIM * A_STRIDE)      // 17408 words
#define BW (DC * TKT)             // 2048 words per buffer
#define SMEM_WORDS (AW + NBUF * BW + 16)
#define SMEM_BYTES (SMEM_WORDS * 4)   // ~102.5 KB -> 2 CTAs/SM

__device__ float  d_xtT[(size_t)NROWS * DDIM];   // [rbi][d][row64] fp32
__device__ float  d_ctT[(size_t)DDIM * KCB];     // [d][col] fp32
__device__ float  d_hist[KCB];
__device__ int    d_cnt[NROWS];
__device__ int    d_gmax[NROWS];                 // ordered-int per-row running max
__device__ int    d_cand[NROWS * SLOTS];
__device__ double d_sqsum;
__device__ int    d_wq;

// ---------------------------------------------------------------------------
// helpers
// ---------------------------------------------------------------------------
__device__ __forceinline__ uint32_t smem_u32(const void* p) {
    uint32_t a;
    asm("{ .reg .u64 t; cvta.to.shared.u64 t, %1; cvt.u32.u64 %0, t; }" : "=r"(a) : "l"(p));
    return a;
}
__device__ __forceinline__ void cp_async16(uint32_t dst, const void* src) {
    asm volatile("cp.async.cg.shared.global [%0], [%1], 16;" :: "r"(dst), "l"(src) : "memory");
}
#define CP_COMMIT() asm volatile("cp.async.commit_group;" ::: "memory")
#define CP_WAIT(n)  asm volatile("cp.async.wait_group %0;" :: "n"(n) : "memory")

__device__ __forceinline__ int   fmap(float f)  { int i = __float_as_int(f); return i < 0 ? i ^ 0x7FFFFFFF : i; }
__device__ __forceinline__ float funmap(int u)  { if (u < 0) u ^= 0x7FFFFFFF; return __int_as_float(u); }

__device__ __forceinline__ void fma2(unsigned long long& d, unsigned long long a,
                                     unsigned long long b) {
    asm("fma.rn.f32x2 %0, %1, %2, %0;" : "+l"(d) : "l"(a), "l"(b));
}
__device__ __forceinline__ unsigned long long pack_dup(float f) {
    unsigned long long o;
    unsigned u = __float_as_uint(f);
    asm("mov.b64 %0, {%1, %1};" : "=l"(o) : "r"(u));
    return o;
}
__device__ __forceinline__ void unpack2(unsigned long long v, float& lo, float& hi) {
    unsigned a, b;
    asm("mov.b64 {%0, %1}, %2;" : "=r"(a), "=r"(b) : "l"(v));
    lo = __uint_as_float(a); hi = __uint_as_float(b);
}

// ---------------------------------------------------------------------------
// Kernel 1a: coalesced latent transpose (64x64 smem tiles) + init accumulators
// grid = 256 rbi x 4 dchunk = 1024 blocks
// ---------------------------------------------------------------------------
__global__ __launch_bounds__(256) void k_prep_x(const float* __restrict__ lat) {
    __shared__ float T[64][68];
    const int b = blockIdx.x, tid = threadIdx.x;
    const int rbi = b >> 2, dc = b & 3;

    {   // coalesced read: 64 rows x 64 d
        int row = tid >> 2, cq = tid & 3;
        const float4* src = (const float4*)(lat + ((size_t)(rbi * 64 + row)) * DDIM
                                            + dc * 64 + cq * 16);
#pragma unroll
        for (int i = 0; i < 4; i++) {
            float4 v = src[i];
            T[row][cq * 16 + 4 * i + 0] = v.x;
            T[row][cq * 16 + 4 * i + 1] = v.y;
            T[row][cq * 16 + 4 * i + 2] = v.z;
            T[row][cq * 16 + 4 * i + 3] = v.w;
        }
    }
    __syncthreads();
    {   // coalesced write: [d][row]
        int d = tid >> 2, rq = tid & 3;
        float4* dst = (float4*)(d_xtT + ((size_t)rbi * DDIM + dc * 64 + d) * 64 + rq * 16);
#pragma unroll
        for (int i = 0; i < 4; i++) {
            float4 v;
            v.x = T[rq * 16 + 4 * i + 0][d];
            v.y = T[rq * 16 + 4 * i + 1][d];
            v.z = T[rq * 16 + 4 * i + 2][d];
            v.w = T[rq * 16 + 4 * i + 3][d];
            dst[i] = v;
        }
    }
    int g = b * 256 + tid;      // 262144 threads
    if (g < KCB)   d_hist[g] = 0.f;
    if (g < NROWS) { d_cnt[g] = 0; d_gmax[g] = fmap(-3.0e38f); }
    if (g == 0)  { d_sqsum = 0.0; d_wq = 0; }
}

// ---------------------------------------------------------------------------
// Kernel 1b: coalesced codebook transpose (64x64 smem tiles)
// grid = 128 colblk x 4 dchunk = 512 blocks
// ---------------------------------------------------------------------------
__global__ __launch_bounds__(256) void k_prep_c(const float* __restrict__ cb) {
    __shared__ float T[64][68];
    const int b = blockIdx.x, tid = threadIdx.x;
    const int cbk = b >> 2, dc = b & 3;

    {   // coalesced read: 64 cols x 64 d
        int col = tid >> 2, cq = tid & 3;
        const float4* src = (const float4*)(cb + ((size_t)(cbk * 64 + col)) * DDIM
                                            + dc * 64 + cq * 16);
#pragma unroll
        for (int i = 0; i < 4; i++) {
            float4 v = src[i];
            T[col][cq * 16 + 4 * i + 0] = v.x;
            T[col][cq * 16 + 4 * i + 1] = v.y;
            T[col][cq * 16 + 4 * i + 2] = v.z;
            T[col][cq * 16 + 4 * i + 3] = v.w;
        }
    }
    __syncthreads();
    {   // coalesced write: [d][col]
        int d = tid >> 2, colq = tid & 3;
        float4* dst = (float4*)(d_ctT + (size_t)(dc * 64 + d) * KCB + cbk * 64 + colq * 16);
#pragma unroll
        for (int i = 0; i < 4; i++) {
            float4 v;
            v.x = T[colq * 16 + 4 * i + 0][d];
            v.y = T[colq * 16 + 4 * i + 1][d];
            v.z = T[colq * 16 + 4 * i + 2][d];
            v.w = T[colq * 16 + 4 * i + 3][d];
            dst[i] = v;
        }
    }
}

// ---------------------------------------------------------------------------
// Kernel 2: persistent work-queue FFMA2 scan, 2 CTAs/SM, 4-deep cp.async ring
// unit = 64 rows x 1024 codes; thread tile 4 rows x 8 cols.
// Candidate threshold from GLOBAL per-row running max (atomicMax return),
// so cross-slice maxima suppress hopeless per-slice candidates.
// ---------------------------------------------------------------------------
#define ISSUE_B(s_) do {                                                        \
    int t_ = (s_) >> 4, c_ = (s_) & 15, buf_ = (s_) & (NBUF - 1);               \
    const float* gB_ = d_ctT + (size_t)(c_ * DC) * KCB + ksl * KSLICE + t_ * TKT; \
    _Pragma("unroll")                                                           \
    for (int i_ = 0; i_ < 2; i_++) {                                            \
        int s2_ = tid + i_ * 256;                                               \
        int dd_ = s2_ >> 5, ch_ = s2_ & 31;                                     \
        cp_async16(sbB + (uint32_t)(buf_ * BW + dd_ * TKT + ch_ * 4) * 4,       \
                   gB_ + (size_t)dd_ * KCB + ch_ * 4);                          \
    }                                                                           \
    CP_COMMIT();                                                                \
} while (0)

__global__ __launch_bounds__(256, 2) void k_scan_f2() {
    extern __shared__ __align__(16) float smf[];
    float* As = smf;                        // [d][row] stride 68
    float* Bs = smf + AW;                   // NBUF buffers [16 dd][128 col]
    __shared__ int s_unit;

    const int tid = threadIdx.x;
    const int tx = tid & 15, ty = tid >> 4;
    const int lane = tid & 31;
    const uint32_t sbA = smem_u32(As);
    const uint32_t sbB = smem_u32(Bs);

    for (;;) {
        if (tid == 0) s_unit = atomicAdd(&d_wq, 1);
        __syncthreads();
        const int u = s_unit;
        if (u >= NUNITS) break;
        const int rbi = u >> 3, ksl = u & 7;
        const int rowblk = rbi * TM;

        // issue A tile: exactly DDIM*TM/4 = 4096 16B chunks = 16 iterations
        {
            const float* gA = d_xtT + (size_t)rbi * (DDIM * TM);
#pragma unroll
            for (int i = 0; i < 16; i++) {
                int s2 = tid + i * 256;            // 0..4095
                int d = s2 >> 4, rg = s2 & 15;     // d in 0..255, rg in 0..15
                cp_async16(sbA + (uint32_t)(d * A_STRIDE + rg * 4) * 4,
                           gA + (size_t)d * TM + rg * 4);
            }
            CP_COMMIT();
        }
        ISSUE_B(0);
        ISSUE_B(1);
        ISSUE_B(2);

        unsigned long long acc[4][4];
#pragma unroll
        for (int r = 0; r < 4; r++)
#pragma unroll
            for (int j = 0; j < 4; j++) acc[r][j] = 0ull;

        for (int s = 0; s < USTAGES; s++) {
            const int c = s & 15, t = s >> 4;
            const float* B = Bs + (s & (NBUF - 1)) * BW;
            if (s + 2 < USTAGES)      { CP_WAIT(2); }
            else if (s + 1 < USTAGES) { CP_WAIT(1); }
            else                      { CP_WAIT(0); }
            __syncthreads();
            if (s + 3 < USTAGES) ISSUE_B(s + 3);

#pragma unroll
            for (int dd = 0; dd < DC; dd++) {
                float4 af = *(const float4*)(As + (size_t)(c * DC + dd) * A_STRIDE + 4 * ty);
                unsigned long long a0 = pack_dup(af.x), a1 = pack_dup(af.y);
                unsigned long long a2 = pack_dup(af.z), a3 = pack_dup(af.w);
                const float* bp = B + (size_t)dd * TKT;
                ulonglong2 b01 = *(const ulonglong2*)(bp + 4 * tx);
                ulonglong2 b23 = *(const ulonglong2*)(bp + 64 + 4 * tx);
                fma2(acc[0][0], a0, b01.x); fma2(acc[1][0], a1, b01.x);
                fma2(acc[2][0], a2, b01.x); fma2(acc[3][0], a3, b01.x);
                fma2(acc[0][1], a0, b01.y); fma2(acc[1][1], a1, b01.y);
                fma2(acc[2][1], a2, b01.y); fma2(acc[3][1], a3, b01.y);
                fma2(acc[0][2], a0, b23.x); fma2(acc[1][2], a1, b23.x);
                fma2(acc[2][2], a2, b23.x); fma2(acc[3][2], a3, b23.x);
                fma2(acc[0][3], a0, b23.y); fma2(acc[1][3], a1, b23.y);
                fma2(acc[2][3], a2, b23.y); fma2(acc[3][3], a3, b23.y);
            }

            if (c == 15) {      // end of 128-col k-tile: max + collect + reset
                const int kbase = ksl * KSLICE + t * TKT;
#pragma unroll
                for (int r = 0; r < 4; r++) {
                    float v8[8];
#pragma unroll
                    for (int j = 0; j < 4; j++) {
                        unpack2(acc[r][j], v8[2 * j], v8[2 * j + 1]);
                        acc[r][j] = 0ull;
                    }
                    float mx = v8[0];
#pragma unroll
                    for (int cc = 1; cc < 8; cc++) mx = fmaxf(mx, v8[cc]);
                    mx = fmaxf(mx, __shfl_xor_sync(0xffffffffu, mx, 1));
                    mx = fmaxf(mx, __shfl_xor_sync(0xffffffffu, mx, 2));
                    mx = fmaxf(mx, __shfl_xor_sync(0xffffffffu, mx, 4));
                    mx = fmaxf(mx, __shfl_xor_sync(0xffffffffu, mx, 8));
                    const int grow = rowblk + 4 * ty + r;
                    int gold = 0;
                    if (tx == 0) gold = atomicMax(&d_gmax[grow], fmap(mx));
                    gold = __shfl_sync(0xffffffffu, gold, lane & 0x10);
                    // known global max so far (monotone): stale only over-collects;
                    // own tile max included so the argmax is always collected
                    const float thr = fmaxf(funmap(gold), mx) - EPS;
#pragma unroll
                    for (int cc = 0; cc < 8; cc++) {
                        if (v8[cc] > thr) {
                            int pos = atomicAdd(&d_cnt[grow], 1);
                            int col = (cc < 4) ? (kbase + 4 * tx + cc)
                                               : (kbase + 64 + 4 * tx + (cc - 4));
                            if (pos < SLOTS)
                                d_cand[grow * SLOTS + pos] = col;
                        }
                    }
                }
            }
        }
    }
}

// ---------------------------------------------------------------------------
// Kernel 3: exact re-rank (half-warp per candidate, compensated fp32 dots)
// + fused gather / MSE partials / histogram.
// q = fl( fl(xn2+cn2) - 2*dot_f ); cn2 < half-ulp(xn2) => dropped (validated
// bit-identical). Compensated dot is correctly rounded (order-independent).
// Argmin with lowest-index ties.
// ---------------------------------------------------------------------------
__global__ __launch_bounds__(256) void k_exact_g(const float* __restrict__ lat,
                                                 const float* __restrict__ mask,
                                                 const float* __restrict__ cb,
                                                 float* __restrict__ out) {
    __shared__ float wsum[8];
    const int tid = threadIdx.x;
    const int lane = tid & 31, w = tid >> 5;
    const int hw = lane >> 4, hl = lane & 15;     // half-warp id, half-lane
    const int row = blockIdx.x * 8 + w;

    float x[16];
    {
        const float4* xr = (const float4*)(lat + (size_t)row * DDIM);
#pragma unroll
        for (int i = 0; i < 4; i++) {
            float4 v = xr[hl * 4 + i];
            x[4 * i + 0] = v.x; x[4 * i + 1] = v.y;
            x[4 * i + 2] = v.z; x[4 * i + 3] = v.w;
        }
    }
    double xs = 0.0;
#pragma unroll
    for (int i = 0; i < 16; i++) xs += (double)x[i] * (double)x[i];
#pragma unroll
    for (int o = 8; o; o >>= 1) xs += __shfl_xor_sync(0xffffffffu, xs, o);
    float xn2 = (float)xs;

    int   n     = d_cnt[row];
    bool  fallb = (n > SLOTS);
    int   ncand = fallb ? KCB : n;

    float bestq = 3.4e38f;
    int   besti = 0x7FFFFFFF;

    for (int c = 0; c < ncand; c += 2) {
        const int  ci  = c + hw;
        const bool act = (ci < ncand);
        const int  idx = act ? (fallb ? ci : d_cand[row * SLOTS + ci]) : 0;
        const float4* cr = (const float4*)(cb + (size_t)idx * DDIM);

        float hi = 0.f, co = 0.f;
#pragma unroll
        for (int i = 0; i < 4; i++) {
            float4 v = cr[hl * 4 + i];
            float cv[4] = {v.x, v.y, v.z, v.w};
#pragma unroll
            for (int k = 0; k < 4; k++) {
                float xx = x[4 * i + k];
                float p = __fmul_rn(xx, cv[k]);
                float e = __fmaf_rn(xx, cv[k], -p);
                float t = __fadd_rn(hi, p);
                float z = __fsub_rn(t, hi);
                float q2 = __fadd_rn(__fsub_rn(hi, __fsub_rn(t, z)), __fsub_rn(p, z));
                hi = t; co = __fadd_rn(co, __fadd_rn(q2, e));
            }
        }
#pragma unroll
        for (int o = 8; o; o >>= 1) {
            float h2 = __shfl_xor_sync(0xffffffffu, hi, o);
            float c2 = __shfl_xor_sync(0xffffffffu, co, o);
            float t = __fadd_rn(hi, h2);
            float z = __fsub_rn(t, hi);
            float q2 = __fadd_rn(__fsub_rn(hi, __fsub_rn(t, z)), __fsub_rn(h2, z));
            hi = t; co = __fadd_rn(co, __fadd_rn(c2, q2));
        }
        if (hl == 0 && act) {
            float df = __fadd_rn(hi, co);
            float q  = __fadd_rn(xn2, -__fmul_rn(2.f, df));
            if (q < bestq || (q == bestq && idx < besti)) { bestq = q; besti = idx; }
        }
    }
    {
        float q1 = __shfl_sync(0xffffffffu, bestq, 16);
        int   i1 = __shfl_sync(0xffffffffu, besti, 16);
        if (lane == 0) {
            if (q1 < bestq || (q1 == bestq && i1 < besti)) { bestq = q1; besti = i1; }
            out[row] = (float)besti;
        }
    }
    const int bi = __shfl_sync(0xffffffffu, besti, 0);

    // fused gather: quantized + st_quantized + MSE partial + histogram
    {
        const float4* xr = (const float4*)(lat + (size_t)row * DDIM);
        const float4* c4 = (const float4*)(cb + (size_t)bi * DDIM);
        float4* q4  = (float4*)(out + OFF_Q  + (size_t)row * DDIM);
        float4* st4 = (float4*)(out + OFF_ST + (size_t)row * DDIM);
        float s = 0.f;
#pragma unroll
        for (int i = lane; i < DDIM / 4; i += 32) {
            float4 cv = c4[i], xv = xr[i];
            q4[i]  = cv;
            st4[i] = cv;
            float d0 = xv.x - cv.x, d1 = xv.y - cv.y;
            float d2 = xv.z - cv.z, d3 = xv.w - cv.w;
            s += d0 * d0 + d1 * d1 + d2 * d2 + d3 * d3;
        }
#pragma unroll
        for (int o = 16; o; o >>= 1) s += __shfl_xor_sync(0xffffffffu, s, o);
        if (lane == 0) {
            wsum[w] = s;
            atomicAdd(&d_hist[bi], mask[row]);
        }
    }
    __syncthreads();
    if (tid == 0) {
        double t = 0.0;
#pragma unroll
        for (int i = 0; i < 8; i++) t += (double)wsum[i];
        atomicAdd(&d_sqsum, t);
    }
}

// ---------------------------------------------------------------------------
// Kernel 4: finalize losses + perplexity
// ---------------------------------------------------------------------------
__global__ void k_final(const float* __restrict__ mask, float* __restrict__ out) {
    __shared__ float sh[256];
    const int tid = threadIdx.x;

    float m = 0.f;
    for (int i = tid; i < NROWS; i += 256) m += mask[i];
    sh[tid] = m; __syncthreads();
    for (int o = 128; o; o >>= 1) { if (tid < o) sh[tid] += sh[tid + o]; __syncthreads(); }
    float denom = fmaxf(sh[0], 1.0f);
    __syncthreads();

    float e = 0.f;
    for (int k2 = tid; k2 < KCB; k2 += 256) {
        float p = d_hist[k2] / denom;
        e += p * logf(p + 1e-8f);
    }
    sh[tid] = e; __syncthreads();
    for (int o = 128; o; o >>= 1) { if (tid < o) sh[tid] += sh[tid + o]; __syncthreads(); }

    if (tid == 0) {
        double mse = d_sqsum / (double)((size_t)NROWS * DDIM);
        out[OFF_SC + 0] = (float)(mse * 0.25);
        out[OFF_SC + 1] = (float)mse;
        out[OFF_SC + 2] = expf(-sh[0]);
    }
}

// ---------------------------------------------------------------------------
extern "C" void kernel_launch(void* const* d_in, const int* in_sizes, int n_in,
                              void* d_out, int out_size) {
    const float* lat  = (const float*)d_in[0];
    const float* mask = (const float*)d_in[1];
    const float* cb   = (const float*)d_in[2];
    float* out = (float*)d_out;

    cudaFuncSetAttribute(k_scan_f2, cudaFuncAttributeMaxDynamicSharedMemorySize, SMEM_BYTES);

    k_prep_x <<<NRB * 4, 256>>>(lat);
    k_prep_c <<<(KCB / 64) * 4, 256>>>(cb);
    k_scan_f2<<<GRID_SCAN, 256, SMEM_BYTES>>>();
    k_exact_g<<<NROWS / 8, 256>>>(lat, mask, cb, out);
    k_final  <<<1, 256>>>(mask, out);
}